// round 15
// baseline (speedup 1.0000x reference)
#include <cuda_runtime.h>
#include <cuda.h>
#include <cuda_fp16.h>
#include <cstdint>

// ===================== constants =====================
#define NNODES   16384
#define HDIM     128
#define TILE_M   128
#define TILE_N   128
#define KSUPER   64             // K elems per super-stage (2 fp32 A boxes + 1 fp16 B box)
#define SSTAGES  4
#define SITERS   (NNODES / KSUPER)   // 256

#define A_SS_BYTES (TILE_M * KSUPER * 4)   // 32768 (fp32)
#define B_SS_BYTES (TILE_N * KSUPER * 2)   // 16384 (fp16)
#define SS_TX      (A_SS_BYTES + B_SS_BYTES)  // 49152

// smem layout (dynamic)
#define SM_FULL    0      // SSTAGES mbarriers (8B each)
#define SM_DONE    64     // SSTAGES mbarriers
#define SM_A       1024
#define SM_B       (SM_A + SSTAGES * A_SS_BYTES)     // 132096
#define SMEM_TOTAL (SM_B + SSTAGES * B_SS_BYTES)     // 197632

#define BIG_THREADS 288   // warps 0-7 compute (4 tiles 64x64, k-split pairs), warp 8 TMA

#define RED_STRIDE 72     // padded fp32 row stride for partial-acc reduction

// in_gemm smem: w tile 128x128 + x tile 128x129 (pad -> conflict-free)
#define XS_PAD  129
#define IN_SMEM ((HDIM * HDIM + HDIM * XS_PAD) * 4)   // 131584

// scratch (allocation-free rule: __device__ globals)
__device__ __align__(1024) __half g_bufB[128UL * 16384];  // t1^T / t2^T  [H][N] fp16
__device__ __align__(1024) float  g_bufH[16384UL * 128];  // h1           [N][H]

// ===================== PTX helpers =====================
__device__ __forceinline__ uint32_t smem_u32(const void* p) {
    uint32_t a;
    asm("{ .reg .u64 t; cvta.to.shared.u64 t, %1; cvt.u32.u64 %0, t; }" : "=r"(a) : "l"(p));
    return a;
}

#define MBAR_INIT(addr, cnt) \
    asm volatile("mbarrier.init.shared.b64 [%0], %1;" :: "r"(addr), "r"(cnt) : "memory")
#define MBAR_EXPECT_TX(addr, bytes) \
    asm volatile("mbarrier.arrive.expect_tx.shared.b64 _, [%0], %1;" :: "r"(addr), "r"(bytes) : "memory")
#define MBAR_ARRIVE(addr) \
    asm volatile("mbarrier.arrive.shared.b64 _, [%0];" :: "r"(addr) : "memory")
#define BAR_SYNC(id, n) \
    asm volatile("bar.sync %0, %1;" :: "r"(id), "r"(n) : "memory")

#define MBAR_WAIT(addr, parity) do {                                            \
    uint32_t _m = (addr), _p = (parity), _d;                                    \
    asm volatile("{\n\t.reg .pred p;\n\t"                                       \
        "mbarrier.try_wait.parity.acquire.cta.shared::cta.b64 p, [%1], %2;\n\t" \
        "selp.b32 %0, 1, 0, p;\n\t}" : "=r"(_d) : "r"(_m), "r"(_p) : "memory"); \
    if (!_d) {                                                                  \
        asm volatile("{\n\t.reg .pred P1;\n\t"                                  \
        "WL%=:\n\t"                                                             \
        "mbarrier.try_wait.parity.acquire.cta.shared::cta.b64 P1, [%0], %1, 0x989680;\n\t" \
        "@P1 bra.uni WD%=;\n\t"                                                 \
        "bra.uni WL%=;\n\t"                                                     \
        "WD%=:\n\t}" :: "r"(_m), "r"(_p) : "memory");                           \
    } } while (0)

__device__ __forceinline__ void tma_2d(uint32_t smem_dst, const CUtensorMap* map,
                                       int32_t cx, int32_t cy, uint32_t mbar) {
    asm volatile(
        "cp.async.bulk.tensor.2d.shared::cta.global.tile.mbarrier::complete_tx::bytes "
        "[%0], [%1, {%2, %3}], [%4];"
        :: "r"(smem_dst), "l"(map), "r"(cx), "r"(cy), "r"(mbar) : "memory");
}

// pack two fp32 -> f16x2 {lo=a, hi=b}
__device__ __forceinline__ uint32_t pack_f16x2(float a, float b) {
    uint32_t r;
    asm("cvt.rn.f16x2.f32 %0, %1, %2;" : "=r"(r) : "f"(b), "f"(a));
    return r;
}

__device__ __forceinline__ void mma_f16(float* c, const uint32_t* a, uint32_t b0, uint32_t b1) {
    asm volatile("mma.sync.aligned.m16n8k16.row.col.f32.f16.f16.f32 "
        "{%0,%1,%2,%3}, {%4,%5,%6,%7}, {%8,%9}, {%0,%1,%2,%3};"
        : "+f"(c[0]), "+f"(c[1]), "+f"(c[2]), "+f"(c[3])
        : "r"(a[0]), "r"(a[1]), "r"(a[2]), "r"(a[3]), "r"(b0), "r"(b1));
}

__device__ __forceinline__ float shfl_xor_f(float v, int m) {
    float r;
    asm("shfl.sync.bfly.b32 %0, %1, %2, 0x1F, 0xFFFFFFFF;" : "=f"(r) : "f"(v), "r"(m));
    return r;
}

// ===================== big GEMM body (k-split pairs) =====================
// out[m][n] = relu(bias[n] + sum_k A[m][k]*Bt[n][k])
// 8 compute warps = 4 tiles (2m x 2n, 64x64 each); within a tile, warp `par`
// consumes only K-box `par` (32 of 64 K per stage) -> B crossbar redundancy
// halves (4x -> 2x). MMA-first lookahead hides the per-stage FULL wait.
// Partial accumulators reduced via recycled pipeline smem at the end.
// HEAD=0: write relu(h+bias) fp32 tile. HEAD=1: fused head out = relu(h)@w3+b3.
template <int HEAD>
__device__ __forceinline__ void big_gemm_body(
    const CUtensorMap& tmA, const CUtensorMap& tmB,
    const float* __restrict__ bias, float* __restrict__ out,
    const float* __restrict__ w3, const float* __restrict__ b3,
    char* smem) {
    const uint32_t base = smem_u32(smem);
    const int tid  = threadIdx.x;
    const int wid  = tid >> 5;
    const int lane = tid & 31;
    const int m0   = blockIdx.x * TILE_M;

    if (tid == 0) {
        for (int s = 0; s < SSTAGES; s++) {
            MBAR_INIT(base + SM_FULL + s * 8, 1);
            MBAR_INIT(base + SM_DONE + s * 8, 8);
        }
    }
    __syncthreads();

    if (wid == 8) {
        // -------- TMA producer --------
        if (lane == 0) {
            const CUtensorMap* pA = &tmA;
            const CUtensorMap* pB = &tmB;
            int ss = 0, ph = 1;
            for (int i = 0; i < SITERS; i++) {
                MBAR_WAIT(base + SM_DONE + ss * 8, (uint32_t)ph);
                uint32_t full = base + SM_FULL + ss * 8;
                MBAR_EXPECT_TX(full, SS_TX);
                uint32_t aslot = base + SM_A + ss * A_SS_BYTES;
                uint32_t bslot = base + SM_B + ss * B_SS_BYTES;
                int k0 = i * KSUPER;
                tma_2d(aslot,         pA, k0,      m0, full);
                tma_2d(aslot + 16384, pA, k0 + 32, m0, full);
                tma_2d(bslot,         pB, k0,      0,  full);
                if (++ss == SSTAGES) { ss = 0; ph ^= 1; }
            }
        }
        return;
    }

    // -------- compute warps --------
    const int g    = lane >> 2;   // 0..7
    const int tg   = lane & 3;    // 0..3
    const int tile = wid >> 1;    // 0..3
    const int par  = wid & 1;     // K-box within stage
    const int wm   = tile >> 1;   // 0..1 (64-row band)
    const int wn   = tile & 1;    // 0..1 (64-col band)
    const uint32_t xorv = (uint32_t)g << 4;
    const int aboxoff = par * 16384;

    const uint32_t rAbase = (uint32_t)(wm * 64 + g) * 128;  // + mi*2048 + h*1024
    const uint32_t rBbase = (uint32_t)(wn * 64 + g) * 128;  // + ni*1024

    // A cols within its par box, per k16 block kb (0/1)
    uint32_t cA[2][2];
    #pragma unroll
    for (int kb = 0; kb < 2; kb++) {
        cA[kb][0] = ((uint32_t)(kb * 64 + 8 * tg)) ^ xorv;
        cA[kb][1] = ((uint32_t)(kb * 64 + 8 * tg + 32)) ^ xorv;
    }
    // B cols per k16 block kb (0/1) within par's k-half
    uint32_t cB[2][2];
    #pragma unroll
    for (int kb = 0; kb < 2; kb++) {
        cB[kb][0] = ((uint32_t)(par * 64 + kb * 32 + 4 * tg)) ^ xorv;
        cB[kb][1] = ((uint32_t)(par * 64 + kb * 32 + 16 + 4 * tg)) ^ xorv;
    }

    float acc[4][8][4];
    #pragma unroll
    for (int mi = 0; mi < 4; mi++)
        #pragma unroll
        for (int ni = 0; ni < 8; ni++)
            #pragma unroll
            for (int q = 0; q < 4; q++) acc[mi][ni][q] = 0.0f;

    uint32_t Af[2][4][4];
    uint32_t Bf[2][8][2];

    auto ldA = [&](uint32_t af[4][4], const char* astg, int kb) {
        const char* ab = astg + aboxoff;
        const uint32_t* c = cA[kb];
        #pragma unroll
        for (int mi = 0; mi < 4; mi++) {
            const char* r0 = ab + rAbase + mi * 2048;
            uint2 lo0 = *(const uint2*)(r0 + c[0]);
            uint2 lo1 = *(const uint2*)(r0 + 1024 + c[0]);
            uint2 hi0 = *(const uint2*)(r0 + c[1]);
            uint2 hi1 = *(const uint2*)(r0 + 1024 + c[1]);
            af[mi][0] = pack_f16x2(__uint_as_float(lo0.x), __uint_as_float(lo0.y));
            af[mi][1] = pack_f16x2(__uint_as_float(lo1.x), __uint_as_float(lo1.y));
            af[mi][2] = pack_f16x2(__uint_as_float(hi0.x), __uint_as_float(hi0.y));
            af[mi][3] = pack_f16x2(__uint_as_float(hi1.x), __uint_as_float(hi1.y));
        }
    };
    auto ldB = [&](uint32_t bf[8][2], const char* bstg, int kb) {
        #pragma unroll
        for (int ni = 0; ni < 8; ni++) {
            bf[ni][0] = *(const uint32_t*)(bstg + rBbase + ni * 1024 + cB[kb][0]);
            bf[ni][1] = *(const uint32_t*)(bstg + rBbase + ni * 1024 + cB[kb][1]);
        }
    };
    auto mmab = [&](const uint32_t af[4][4], const uint32_t bf[8][2]) {
        #pragma unroll
        for (int mi = 0; mi < 4; mi++)
            #pragma unroll
            for (int ni = 0; ni < 8; ni++)
                mma_f16(acc[mi][ni], af[mi], bf[ni][0], bf[ni][1]);
    };

    int ss = 0, ph = 0;
    const char* astg = smem + SM_A;
    const char* bstg = smem + SM_B;

    MBAR_WAIT(base + SM_FULL, 0u);
    ldB(Bf[0], bstg, 0);
    ldA(Af[0], astg, 0);
    ldB(Bf[1], bstg, 1);
    ldA(Af[1], astg, 1);

    for (int i = 0; i < SITERS; i++) {
        mmab(Af[0], Bf[0]);
        int ssn = ss + 1, phn = ph;
        if (ssn == SSTAGES) { ssn = 0; phn ^= 1; }
        const char* nastg = smem + SM_A + ssn * A_SS_BYTES;
        const char* nbstg = smem + SM_B + ssn * B_SS_BYTES;
        if (i < SITERS - 1) {
            MBAR_WAIT(base + SM_FULL + ssn * 8, (uint32_t)phn);
            ldB(Bf[0], nbstg, 0);
            ldA(Af[0], nastg, 0);
        }
        mmab(Af[1], Bf[1]);
        if (lane == 0) MBAR_ARRIVE(base + SM_DONE + ss * 8);
        if (i < SITERS - 1) {
            ldB(Bf[1], nbstg, 1);
            ldA(Af[1], nastg, 1);
        }
        astg = nastg; bstg = nbstg; ss = ssn; ph = phn;
    }

    // -------- k-split pair reduction via recycled pipeline smem --------
    BAR_SYNC(1, 256);   // all compute warps done reading pipeline smem
    float* red = (float*)(smem + SM_A) + tile * (64 * RED_STRIDE);
    if (par == 0) {
        #pragma unroll
        for (int mi = 0; mi < 4; mi++) {
            const int lr = mi * 16 + g;
            #pragma unroll
            for (int ni = 0; ni < 8; ni++) {
                float2 v0, v1;
                v0.x = acc[mi][ni][0]; v0.y = acc[mi][ni][1];
                v1.x = acc[mi][ni][2]; v1.y = acc[mi][ni][3];
                *reinterpret_cast<float2*>(red + lr * RED_STRIDE + ni * 8 + tg * 2) = v0;
                *reinterpret_cast<float2*>(red + (lr + 8) * RED_STRIDE + ni * 8 + tg * 2) = v1;
            }
        }
    }
    BAR_SYNC(1, 256);

    if (HEAD == 0) {
        if (par == 1) {
            #pragma unroll
            for (int ni = 0; ni < 8; ni++) {
                const int c0 = wn * 64 + ni * 8 + tg * 2;
                const float bb0 = __ldg(&bias[c0]);
                const float bb1 = __ldg(&bias[c0 + 1]);
                #pragma unroll
                for (int mi = 0; mi < 4; mi++) {
                    const int lr = mi * 16 + g;
                    const int r0 = m0 + wm * 64 + lr;
                    float2 p0 = *reinterpret_cast<float2*>(red + lr * RED_STRIDE + ni * 8 + tg * 2);
                    float2 p1 = *reinterpret_cast<float2*>(red + (lr + 8) * RED_STRIDE + ni * 8 + tg * 2);
                    float2 v0, v1;
                    v0.x = fmaxf(acc[mi][ni][0] + p0.x + bb0, 0.0f);
                    v0.y = fmaxf(acc[mi][ni][1] + p0.y + bb1, 0.0f);
                    v1.x = fmaxf(acc[mi][ni][2] + p1.x + bb0, 0.0f);
                    v1.y = fmaxf(acc[mi][ni][3] + p1.y + bb1, 0.0f);
                    *reinterpret_cast<float2*>(out + (size_t)r0 * HDIM + c0) = v0;
                    *reinterpret_cast<float2*>(out + (size_t)(r0 + 8) * HDIM + c0) = v1;
                }
            }
        }
    } else {
        // fused head: out[m][c] = b3[c] + sum_n relu(h[m][n]+bias[n]) * w3[n][c]
        float s[4][2][2];   // [mi][h-half][class]
        if (par == 1) {
            #pragma unroll
            for (int mi = 0; mi < 4; mi++)
                #pragma unroll
                for (int h = 0; h < 2; h++) { s[mi][h][0] = 0.0f; s[mi][h][1] = 0.0f; }
            #pragma unroll
            for (int ni = 0; ni < 8; ni++) {
                const int c0 = wn * 64 + ni * 8 + tg * 2;
                const float bb0 = __ldg(&bias[c0]);
                const float bb1 = __ldg(&bias[c0 + 1]);
                const float w00 = __ldg(&w3[c0 * 2 + 0]),       w01 = __ldg(&w3[c0 * 2 + 1]);
                const float w10 = __ldg(&w3[(c0 + 1) * 2 + 0]), w11 = __ldg(&w3[(c0 + 1) * 2 + 1]);
                #pragma unroll
                for (int mi = 0; mi < 4; mi++) {
                    const int lr = mi * 16 + g;
                    float2 p0 = *reinterpret_cast<float2*>(red + lr * RED_STRIDE + ni * 8 + tg * 2);
                    float2 p1 = *reinterpret_cast<float2*>(red + (lr + 8) * RED_STRIDE + ni * 8 + tg * 2);
                    float h0 = fmaxf(acc[mi][ni][0] + p0.x + bb0, 0.0f);
                    float h1 = fmaxf(acc[mi][ni][1] + p0.y + bb1, 0.0f);
                    s[mi][0][0] += h0 * w00 + h1 * w10;
                    s[mi][0][1] += h0 * w01 + h1 * w11;
                    float h2 = fmaxf(acc[mi][ni][2] + p1.x + bb0, 0.0f);
                    float h3 = fmaxf(acc[mi][ni][3] + p1.y + bb1, 0.0f);
                    s[mi][1][0] += h2 * w00 + h3 * w10;
                    s[mi][1][1] += h2 * w01 + h3 * w11;
                }
            }
            // reduce over tg (4 lanes within each g-group)
            #pragma unroll
            for (int mi = 0; mi < 4; mi++)
                #pragma unroll
                for (int h = 0; h < 2; h++)
                    #pragma unroll
                    for (int c = 0; c < 2; c++) {
                        float v = s[mi][h][c];
                        v += shfl_xor_f(v, 1);
                        v += shfl_xor_f(v, 2);
                        s[mi][h][c] = v;
                    }
        }
        // cross-wn reduction via recycled B-pipeline smem
        float* red2 = (float*)(smem + SM_B);   // [128 rows][2 classes]
        if (par == 1 && wn == 0 && tg == 0) {
            #pragma unroll
            for (int mi = 0; mi < 4; mi++)
                #pragma unroll
                for (int h = 0; h < 2; h++) {
                    const int row = wm * 64 + mi * 16 + h * 8 + g;
                    red2[row * 2 + 0] = s[mi][h][0];
                    red2[row * 2 + 1] = s[mi][h][1];
                }
        }
        BAR_SYNC(1, 256);
        if (par == 1 && wn == 1 && tg == 0) {
            const float bb30 = __ldg(&b3[0]);
            const float bb31 = __ldg(&b3[1]);
            #pragma unroll
            for (int mi = 0; mi < 4; mi++)
                #pragma unroll
                for (int h = 0; h < 2; h++) {
                    const int row = wm * 64 + mi * 16 + h * 8 + g;
                    float2 o;
                    o.x = s[mi][h][0] + red2[row * 2 + 0] + bb30;
                    o.y = s[mi][h][1] + red2[row * 2 + 1] + bb31;
                    *reinterpret_cast<float2*>(out + (size_t)(m0 + row) * 2) = o;
                }
        }
    }
}

__global__ void __launch_bounds__(BIG_THREADS, 1)
gcn_big_gemm(const __grid_constant__ CUtensorMap tmA,
             const __grid_constant__ CUtensorMap tmB,
             const float* __restrict__ bias,
             float* __restrict__ out) {
    extern __shared__ __align__(1024) char smem[];
    big_gemm_body<0>(tmA, tmB, bias, out, nullptr, nullptr, smem);
}

__global__ void __launch_bounds__(BIG_THREADS, 1)
gcn_big_gemm_head(const __grid_constant__ CUtensorMap tmA,
                  const __grid_constant__ CUtensorMap tmB,
                  const float* __restrict__ bias,
                  const float* __restrict__ w3,
                  const float* __restrict__ b3,
                  float* __restrict__ out) {
    extern __shared__ __align__(1024) char smem[];
    big_gemm_body<1>(tmA, tmB, bias, out, w3, b3, smem);
}

// ===================== small GEMM: outT[n][node] = sum_f in[node][f] * w[f][n] =====================
// Output stored as fp16 (RN) = pre-rounded B operand for the big GEMM.
__global__ void __launch_bounds__(256)
gcn_in_gemm(const float* __restrict__ in, const float* __restrict__ w, __half* __restrict__ outT) {
    extern __shared__ float sm[];
    float* ws = sm;                       // [128][128]
    float* xs = sm + HDIM * HDIM;         // [128][129] padded
    const int tid = threadIdx.x;
    const int n0 = blockIdx.x * 128;

    for (int i = tid; i < (HDIM * HDIM) / 4; i += 256)
        reinterpret_cast<float4*>(ws)[i] = reinterpret_cast<const float4*>(w)[i];
    {
        const int col = tid & 127;
        const int r0  = tid >> 7;
        for (int r = r0; r < 128; r += 2)
            xs[r * XS_PAD + col] = in[(size_t)(n0 + r) * HDIM + col];
    }
    __syncthreads();

    const int cg   = tid >> 5;
    const int lane = tid & 31;

    float acc[4][16];
    #pragma unroll
    for (int k = 0; k < 4; k++)
        #pragma unroll
        for (int j = 0; j < 16; j++) acc[k][j] = 0.0f;

    #pragma unroll 4
    for (int f = 0; f < HDIM; f++) {
        float a[4];
        #pragma unroll
        for (int k = 0; k < 4; k++)
            a[k] = xs[(lane + 32 * k) * XS_PAD + f];
        const float4* wr = reinterpret_cast<const float4*>(ws + f * HDIM + cg * 16);
        float4 w0 = wr[0], w1 = wr[1], w2 = wr[2], w3 = wr[3];
        #pragma unroll
        for (int k = 0; k < 4; k++) {
            acc[k][0]  += a[k] * w0.x;  acc[k][1]  += a[k] * w0.y;
            acc[k][2]  += a[k] * w0.z;  acc[k][3]  += a[k] * w0.w;
            acc[k][4]  += a[k] * w1.x;  acc[k][5]  += a[k] * w1.y;
            acc[k][6]  += a[k] * w1.z;  acc[k][7]  += a[k] * w1.w;
            acc[k][8]  += a[k] * w2.x;  acc[k][9]  += a[k] * w2.y;
            acc[k][10] += a[k] * w2.z;  acc[k][11] += a[k] * w2.w;
            acc[k][12] += a[k] * w3.x;  acc[k][13] += a[k] * w3.y;
            acc[k][14] += a[k] * w3.z;  acc[k][15] += a[k] * w3.w;
        }
    }
    #pragma unroll
    for (int j = 0; j < 16; j++) {
        const int col = cg * 16 + j;
        #pragma unroll
        for (int k = 0; k < 4; k++)
            outT[(size_t)col * NNODES + n0 + lane + 32 * k] = __float2half_rn(acc[k][j]);
    }
}

// ===================== host =====================
typedef CUresult (*PFN_encodeTiled)(CUtensorMap*, CUtensorMapDataType, cuuint32_t, void*,
                                    const cuuint64_t*, const cuuint64_t*, const cuuint32_t*,
                                    const cuuint32_t*, CUtensorMapInterleave, CUtensorMapSwizzle,
                                    CUtensorMapL2promotion, CUtensorMapFloatOOBfill);

extern "C" void kernel_launch(void* const* d_in, const int* in_sizes, int n_in,
                              void* d_out, int out_size) {
    const float* x   = (const float*)d_in[0];
    const float* adj = (const float*)d_in[1];
    const float* w1  = (const float*)d_in[2];
    const float* b1  = (const float*)d_in[3];
    const float* w2  = (const float*)d_in[4];
    const float* b2  = (const float*)d_in[5];
    const float* w3  = (const float*)d_in[6];
    const float* b3  = (const float*)d_in[7];
    float* out = (float*)d_out;

    void* bufB = nullptr;
    void* bufH = nullptr;
    cudaGetSymbolAddress(&bufB, g_bufB);
    cudaGetSymbolAddress(&bufH, g_bufH);

    void* fn = nullptr;
    cudaDriverEntryPointQueryResult qres;
    cudaGetDriverEntryPointByVersion("cuTensorMapEncodeTiled", &fn, 12000,
                                     cudaEnableDefault, &qres);
    PFN_encodeTiled encode = (PFN_encodeTiled)fn;

    CUtensorMap tmA{}, tmB{};
    {
        cuuint64_t dims[2]   = {NNODES, NNODES};
        cuuint64_t stride[1] = {NNODES * sizeof(float)};
        cuuint32_t box[2]    = {32, TILE_M};
        cuuint32_t es[2]     = {1, 1};
        encode(&tmA, CU_TENSOR_MAP_DATA_TYPE_FLOAT32, 2, (void*)adj, dims, stride, box, es,
               CU_TENSOR_MAP_INTERLEAVE_NONE, CU_TENSOR_MAP_SWIZZLE_128B,
               CU_TENSOR_MAP_L2_PROMOTION_L2_128B, CU_TENSOR_MAP_FLOAT_OOB_FILL_NONE);
    }
    {
        cuuint64_t dims[2]   = {NNODES, HDIM};
        cuuint64_t stride[1] = {NNODES * sizeof(__half)};
        cuuint32_t box[2]    = {64, TILE_N};   // 64 f16 = 128B rows (SW128)
        cuuint32_t es[2]     = {1, 1};
        encode(&tmB, CU_TENSOR_MAP_DATA_TYPE_FLOAT16, 2, bufB, dims, stride, box, es,
               CU_TENSOR_MAP_INTERLEAVE_NONE, CU_TENSOR_MAP_SWIZZLE_128B,
               CU_TENSOR_MAP_L2_PROMOTION_L2_128B, CU_TENSOR_MAP_FLOAT_OOB_FILL_NONE);
    }

    cudaFuncSetAttribute(gcn_big_gemm, cudaFuncAttributeMaxDynamicSharedMemorySize, SMEM_TOTAL);
    cudaFuncSetAttribute(gcn_big_gemm_head, cudaFuncAttributeMaxDynamicSharedMemorySize, SMEM_TOTAL);
    cudaFuncSetAttribute(gcn_in_gemm, cudaFuncAttributeMaxDynamicSharedMemorySize, IN_SMEM);

    // 1) t1^T (fp16)
    gcn_in_gemm<<<NNODES / 128, 256, IN_SMEM>>>(x, w1, (__half*)bufB);
    // 2) h1 = relu(adj @ t1 + b1)
    gcn_big_gemm<<<NNODES / TILE_M, BIG_THREADS, SMEM_TOTAL>>>(tmA, tmB, b1, (float*)bufH);
    // 3) t2^T (fp16)
    gcn_in_gemm<<<NNODES / 128, 256, IN_SMEM>>>((const float*)bufH, w2, (__half*)bufB);
    // 4) out = relu(adj @ t2 + b2) @ w3 + b3   (head fused into epilogue)
    gcn_big_gemm_head<<<NNODES / TILE_M, BIG_THREADS, SMEM_TOTAL>>>(tmA, tmB, b2, w3, b3, out);
}

// round 16
// speedup vs baseline: 3.8582x; 3.8582x over previous
#include <cuda_runtime.h>
#include <cuda.h>
#include <cuda_fp16.h>
#include <cstdint>

// ===================== constants =====================
#define NNODES   16384
#define HDIM     128
#define TILE_M   128
#define TILE_N   128
#define KSUPER   64             // K elems per super-stage (2 fp32 A boxes + 1 fp16 B box)
#define SSTAGES  4
#define SITERS   (NNODES / KSUPER)   // 256

#define A_SS_BYTES (TILE_M * KSUPER * 4)   // 32768 (fp32)
#define B_SS_BYTES (TILE_N * KSUPER * 2)   // 16384 (fp16)
#define SS_TX      (A_SS_BYTES + B_SS_BYTES)  // 49152

// smem layout (dynamic)
#define SM_FULL    0      // SSTAGES mbarriers (8B each)
#define SM_DONE    64     // SSTAGES mbarriers
#define SM_A       1024
#define SM_B       (SM_A + SSTAGES * A_SS_BYTES)     // 132096
#define SMEM_TOTAL (SM_B + SSTAGES * B_SS_BYTES)     // 197632

#define BIG_THREADS 288   // warps 0-7 compute (4x2 grid of 32x64 tiles), warp 8 TMA

// in_gemm smem: w tile 128x128 + x tile 128x129 (pad -> conflict-free)
#define XS_PAD  129
#define IN_SMEM ((HDIM * HDIM + HDIM * XS_PAD) * 4)   // 131584

// scratch (allocation-free rule: __device__ globals)
__device__ __align__(1024) __half g_bufB[128UL * 16384];  // t1^T / t2^T  [H][N] fp16
__device__ __align__(1024) float  g_bufH[16384UL * 128];  // h1           [N][H]

// ===================== PTX helpers =====================
__device__ __forceinline__ uint32_t smem_u32(const void* p) {
    uint32_t a;
    asm("{ .reg .u64 t; cvta.to.shared.u64 t, %1; cvt.u32.u64 %0, t; }" : "=r"(a) : "l"(p));
    return a;
}

#define MBAR_INIT(addr, cnt) \
    asm volatile("mbarrier.init.shared.b64 [%0], %1;" :: "r"(addr), "r"(cnt) : "memory")
#define MBAR_EXPECT_TX(addr, bytes) \
    asm volatile("mbarrier.arrive.expect_tx.shared.b64 _, [%0], %1;" :: "r"(addr), "r"(bytes) : "memory")
#define MBAR_ARRIVE(addr) \
    asm volatile("mbarrier.arrive.shared.b64 _, [%0];" :: "r"(addr) : "memory")
#define BAR_SYNC(id, n) \
    asm volatile("bar.sync %0, %1;" :: "r"(id), "r"(n) : "memory")

#define MBAR_WAIT(addr, parity) do {                                            \
    uint32_t _m = (addr), _p = (parity), _d;                                    \
    asm volatile("{\n\t.reg .pred p;\n\t"                                       \
        "mbarrier.try_wait.parity.acquire.cta.shared::cta.b64 p, [%1], %2;\n\t" \
        "selp.b32 %0, 1, 0, p;\n\t}" : "=r"(_d) : "r"(_m), "r"(_p) : "memory"); \
    if (!_d) {                                                                  \
        asm volatile("{\n\t.reg .pred P1;\n\t"                                  \
        "WL%=:\n\t"                                                             \
        "mbarrier.try_wait.parity.acquire.cta.shared::cta.b64 P1, [%0], %1, 0x989680;\n\t" \
        "@P1 bra.uni WD%=;\n\t"                                                 \
        "bra.uni WL%=;\n\t"                                                     \
        "WD%=:\n\t}" :: "r"(_m), "r"(_p) : "memory");                           \
    } } while (0)

__device__ __forceinline__ void tma_2d(uint32_t smem_dst, const CUtensorMap* map,
                                       int32_t cx, int32_t cy, uint32_t mbar) {
    asm volatile(
        "cp.async.bulk.tensor.2d.shared::cta.global.tile.mbarrier::complete_tx::bytes "
        "[%0], [%1, {%2, %3}], [%4];"
        :: "r"(smem_dst), "l"(map), "r"(cx), "r"(cy), "r"(mbar) : "memory");
}

// pack two fp32 -> f16x2 {lo=a, hi=b}
__device__ __forceinline__ uint32_t pack_f16x2(float a, float b) {
    uint32_t r;
    asm("cvt.rn.f16x2.f32 %0, %1, %2;" : "=r"(r) : "f"(b), "f"(a));
    return r;
}

__device__ __forceinline__ void mma_f16(float* c, const uint32_t* a, uint32_t b0, uint32_t b1) {
    asm volatile("mma.sync.aligned.m16n8k16.row.col.f32.f16.f16.f32 "
        "{%0,%1,%2,%3}, {%4,%5,%6,%7}, {%8,%9}, {%0,%1,%2,%3};"
        : "+f"(c[0]), "+f"(c[1]), "+f"(c[2]), "+f"(c[3])
        : "r"(a[0]), "r"(a[1]), "r"(a[2]), "r"(a[3]), "r"(b0), "r"(b1));
}

__device__ __forceinline__ float shfl_xor_f(float v, int m) {
    float r;
    asm("shfl.sync.bfly.b32 %0, %1, %2, 0x1F, 0xFFFFFFFF;" : "=f"(r) : "f"(v), "r"(m));
    return r;
}

// ===================== big GEMM mainloop (shared by both variants) =====================
// HEAD=0: epilogue writes relu(acc+bias) fp32 tile to `out` (h1).
// HEAD=1: epilogue computes out[m][c] = b3[c] + sum_n relu(acc+bias)[m][n]*w3[n][c].
template <int HEAD>
__device__ __forceinline__ void big_gemm_body(
    const CUtensorMap& tmA, const CUtensorMap& tmB,
    const float* __restrict__ bias, float* __restrict__ out,
    const float* __restrict__ w3, const float* __restrict__ b3,
    char* smem) {
    const uint32_t base = smem_u32(smem);
    const int tid  = threadIdx.x;
    const int wid  = tid >> 5;
    const int lane = tid & 31;
    const int m0   = blockIdx.x * TILE_M;

    if (tid == 0) {
        for (int s = 0; s < SSTAGES; s++) {
            MBAR_INIT(base + SM_FULL + s * 8, 1);
            MBAR_INIT(base + SM_DONE + s * 8, 8);
        }
    }
    __syncthreads();

    if (wid == 8) {
        // -------- TMA producer --------
        if (lane == 0) {
            const CUtensorMap* pA = &tmA;
            const CUtensorMap* pB = &tmB;
            int ss = 0, ph = 1;
            for (int i = 0; i < SITERS; i++) {
                MBAR_WAIT(base + SM_DONE + ss * 8, (uint32_t)ph);
                uint32_t full = base + SM_FULL + ss * 8;
                MBAR_EXPECT_TX(full, SS_TX);
                uint32_t aslot = base + SM_A + ss * A_SS_BYTES;
                uint32_t bslot = base + SM_B + ss * B_SS_BYTES;
                int k0 = i * KSUPER;
                tma_2d(aslot,         pA, k0,      m0, full);
                tma_2d(aslot + 16384, pA, k0 + 32, m0, full);
                tma_2d(bslot,         pB, k0,      0,  full);
                if (++ss == SSTAGES) { ss = 0; ph ^= 1; }
            }
        }
        return;
    }

    // -------- compute warps --------
    const int g  = lane >> 2;     // 0..7
    const int tg = lane & 3;      // 0..3
    const int wm = wid >> 1;      // 0..3  (m: 32-row band)
    const int wn = wid & 1;       // 0..1  (n: 64-col band)
    const uint32_t xorv = (uint32_t)g << 4;

    const uint32_t rAbase = (uint32_t)(wm * 32 + g) * 128;
    const uint32_t rBbase = (uint32_t)(wn * 64 + g) * 128;

    uint32_t cA[2][2];
    #pragma unroll
    for (int s = 0; s < 2; s++) {
        cA[s][0] = ((uint32_t)(s * 64 + 8 * tg)) ^ xorv;
        cA[s][1] = ((uint32_t)(s * 64 + 8 * tg + 32)) ^ xorv;
    }
    uint32_t cB[4][2];
    #pragma unroll
    for (int kb = 0; kb < 4; kb++) {
        cB[kb][0] = ((uint32_t)(32 * kb + 4 * tg)) ^ xorv;
        cB[kb][1] = ((uint32_t)(32 * kb + 16 + 4 * tg)) ^ xorv;
    }

    float acc[2][8][4];
    #pragma unroll
    for (int mi = 0; mi < 2; mi++)
        #pragma unroll
        for (int ni = 0; ni < 8; ni++)
            #pragma unroll
            for (int q = 0; q < 4; q++) acc[mi][ni][q] = 0.0f;

    uint32_t Af[2][2][4];
    uint32_t Bf[2][8][2];

    auto ldA = [&](uint32_t af[2][4], const char* astg, int kb) {
        const char* ab = astg + ((kb >> 1) << 14);
        const uint32_t* c = cA[kb & 1];
        #pragma unroll
        for (int mi = 0; mi < 2; mi++) {
            const char* r0 = ab + rAbase + mi * 2048;
            uint2 lo0 = *(const uint2*)(r0 + c[0]);
            uint2 lo1 = *(const uint2*)(r0 + 1024 + c[0]);
            uint2 hi0 = *(const uint2*)(r0 + c[1]);
            uint2 hi1 = *(const uint2*)(r0 + 1024 + c[1]);
            af[mi][0] = pack_f16x2(__uint_as_float(lo0.x), __uint_as_float(lo0.y));
            af[mi][1] = pack_f16x2(__uint_as_float(lo1.x), __uint_as_float(lo1.y));
            af[mi][2] = pack_f16x2(__uint_as_float(hi0.x), __uint_as_float(hi0.y));
            af[mi][3] = pack_f16x2(__uint_as_float(hi1.x), __uint_as_float(hi1.y));
        }
    };
    auto ldB = [&](uint32_t bf[8][2], const char* bstg, int kb) {
        #pragma unroll
        for (int ni = 0; ni < 8; ni++) {
            bf[ni][0] = *(const uint32_t*)(bstg + rBbase + ni * 1024 + cB[kb][0]);
            bf[ni][1] = *(const uint32_t*)(bstg + rBbase + ni * 1024 + cB[kb][1]);
        }
    };
    auto mmab = [&](const uint32_t af[2][4], const uint32_t bf[8][2]) {
        #pragma unroll
        for (int mi = 0; mi < 2; mi++)
            #pragma unroll
            for (int ni = 0; ni < 8; ni++)
                mma_f16(acc[mi][ni], af[mi], bf[ni][0], bf[ni][1]);
    };

    int ss = 0, ph = 0;
    const char* astg = smem + SM_A;
    const char* bstg = smem + SM_B;

    MBAR_WAIT(base + SM_FULL, 0u);
    ldB(Bf[0], bstg, 0);
    ldA(Af[0], astg, 0);
    ldB(Bf[1], bstg, 1);
    ldA(Af[1], astg, 1);

    for (int i = 0; i < SITERS; i++) {
        mmab(Af[0], Bf[0]);
        ldB(Bf[0], bstg, 2);
        ldA(Af[0], astg, 2);
        mmab(Af[1], Bf[1]);
        ldB(Bf[1], bstg, 3);
        ldA(Af[1], astg, 3);
        mmab(Af[0], Bf[0]);
        int ssn = ss + 1, phn = ph;
        if (ssn == SSTAGES) { ssn = 0; phn ^= 1; }
        const char* nastg = smem + SM_A + ssn * A_SS_BYTES;
        const char* nbstg = smem + SM_B + ssn * B_SS_BYTES;
        if (i < SITERS - 1) {
            MBAR_WAIT(base + SM_FULL + ssn * 8, (uint32_t)phn);
            ldB(Bf[0], nbstg, 0);
            ldA(Af[0], nastg, 0);
        }
        mmab(Af[1], Bf[1]);
        if (lane == 0) MBAR_ARRIVE(base + SM_DONE + ss * 8);
        if (i < SITERS - 1) {
            ldB(Bf[1], nbstg, 1);
            ldA(Af[1], nastg, 1);
        }
        astg = nastg; bstg = nbstg; ss = ssn; ph = phn;
    }

    if (HEAD == 0) {
        // -------- epilogue: bias + relu, write fp32 h tile --------
        #pragma unroll
        for (int ni = 0; ni < 8; ni++) {
            const int c0 = wn * 64 + ni * 8 + tg * 2;
            const float bb0 = __ldg(&bias[c0]);
            const float bb1 = __ldg(&bias[c0 + 1]);
            #pragma unroll
            for (int mi = 0; mi < 2; mi++) {
                const int r0 = m0 + wm * 32 + mi * 16 + g;
                float2 v0, v1;
                v0.x = fmaxf(acc[mi][ni][0] + bb0, 0.0f);
                v0.y = fmaxf(acc[mi][ni][1] + bb1, 0.0f);
                v1.x = fmaxf(acc[mi][ni][2] + bb0, 0.0f);
                v1.y = fmaxf(acc[mi][ni][3] + bb1, 0.0f);
                *reinterpret_cast<float2*>(out + (size_t)r0 * HDIM + c0) = v0;
                *reinterpret_cast<float2*>(out + (size_t)(r0 + 8) * HDIM + c0) = v1;
            }
        }
    } else {
        // -------- fused head epilogue: out[m][c] = b3[c] + sum_n relu(h)[m][n]*w3[n][c]
        float s[2][2][2];   // [mi][h(0: row r0, 1: row r0+8)][class]
        #pragma unroll
        for (int mi = 0; mi < 2; mi++)
            #pragma unroll
            for (int h = 0; h < 2; h++) { s[mi][h][0] = 0.0f; s[mi][h][1] = 0.0f; }

        #pragma unroll
        for (int ni = 0; ni < 8; ni++) {
            const int c0 = wn * 64 + ni * 8 + tg * 2;
            const float bb0 = __ldg(&bias[c0]);
            const float bb1 = __ldg(&bias[c0 + 1]);
            const float w00 = __ldg(&w3[c0 * 2 + 0]),     w01 = __ldg(&w3[c0 * 2 + 1]);
            const float w10 = __ldg(&w3[(c0 + 1) * 2 + 0]), w11 = __ldg(&w3[(c0 + 1) * 2 + 1]);
            #pragma unroll
            for (int mi = 0; mi < 2; mi++) {
                float h0 = fmaxf(acc[mi][ni][0] + bb0, 0.0f);
                float h1 = fmaxf(acc[mi][ni][1] + bb1, 0.0f);
                s[mi][0][0] += h0 * w00 + h1 * w10;
                s[mi][0][1] += h0 * w01 + h1 * w11;
                float h2 = fmaxf(acc[mi][ni][2] + bb0, 0.0f);
                float h3 = fmaxf(acc[mi][ni][3] + bb1, 0.0f);
                s[mi][1][0] += h2 * w00 + h3 * w10;
                s[mi][1][1] += h2 * w01 + h3 * w11;
            }
        }
        // reduce over tg (4 lanes within each g-group)
        #pragma unroll
        for (int mi = 0; mi < 2; mi++)
            #pragma unroll
            for (int h = 0; h < 2; h++)
                #pragma unroll
                for (int c = 0; c < 2; c++) {
                    float v = s[mi][h][c];
                    v += shfl_xor_f(v, 1);
                    v += shfl_xor_f(v, 2);
                    s[mi][h][c] = v;
                }
        // cross-wn reduction via recycled pipeline smem (TMA warp has exited)
        float* red = (float*)(smem + SM_B);   // [128 rows][2 classes]
        if (wn == 0 && tg == 0) {
            #pragma unroll
            for (int mi = 0; mi < 2; mi++)
                #pragma unroll
                for (int h = 0; h < 2; h++) {
                    const int row = wm * 32 + mi * 16 + h * 8 + g;
                    red[row * 2 + 0] = s[mi][h][0];
                    red[row * 2 + 1] = s[mi][h][1];
                }
        }
        BAR_SYNC(1, 256);
        if (wn == 1 && tg == 0) {
            #pragma unroll
            for (int mi = 0; mi < 2; mi++)
                #pragma unroll
                for (int h = 0; h < 2; h++) {
                    const int row = wm * 32 + mi * 16 + h * 8 + g;
                    float2 o;
                    o.x = s[mi][h][0] + red[row * 2 + 0] + __ldg(&b3[0]);
                    o.y = s[mi][h][1] + red[row * 2 + 1] + __ldg(&b3[1]);
                    *reinterpret_cast<float2*>(out + (size_t)(m0 + row) * 2) = o;
                }
        }
    }
}

__global__ void __launch_bounds__(BIG_THREADS, 1)
gcn_big_gemm(const __grid_constant__ CUtensorMap tmA,
             const __grid_constant__ CUtensorMap tmB,
             const float* __restrict__ bias,
             float* __restrict__ out) {
    extern __shared__ __align__(1024) char smem[];
    big_gemm_body<0>(tmA, tmB, bias, out, nullptr, nullptr, smem);
}

__global__ void __launch_bounds__(BIG_THREADS, 1)
gcn_big_gemm_head(const __grid_constant__ CUtensorMap tmA,
                  const __grid_constant__ CUtensorMap tmB,
                  const float* __restrict__ bias,
                  const float* __restrict__ w3,
                  const float* __restrict__ b3,
                  float* __restrict__ out) {
    extern __shared__ __align__(1024) char smem[];
    big_gemm_body<1>(tmA, tmB, bias, out, w3, b3, smem);
}

// ===================== small GEMM: outT[n][node] = sum_f in[node][f] * w[f][n] =====================
// Output stored as fp16 (RN) = pre-rounded B operand for the big GEMM.
__global__ void __launch_bounds__(256)
gcn_in_gemm(const float* __restrict__ in, const float* __restrict__ w, __half* __restrict__ outT) {
    extern __shared__ float sm[];
    float* ws = sm;                       // [128][128]
    float* xs = sm + HDIM * HDIM;         // [128][129] padded
    const int tid = threadIdx.x;
    const int n0 = blockIdx.x * 128;

    for (int i = tid; i < (HDIM * HDIM) / 4; i += 256)
        reinterpret_cast<float4*>(ws)[i] = reinterpret_cast<const float4*>(w)[i];
    {
        const int col = tid & 127;
        const int r0  = tid >> 7;
        for (int r = r0; r < 128; r += 2)
            xs[r * XS_PAD + col] = in[(size_t)(n0 + r) * HDIM + col];
    }
    __syncthreads();

    const int cg   = tid >> 5;
    const int lane = tid & 31;

    float acc[4][16];
    #pragma unroll
    for (int k = 0; k < 4; k++)
        #pragma unroll
        for (int j = 0; j < 16; j++) acc[k][j] = 0.0f;

    #pragma unroll 8
    for (int f = 0; f < HDIM; f++) {
        float a[4];
        #pragma unroll
        for (int k = 0; k < 4; k++)
            a[k] = xs[(lane + 32 * k) * XS_PAD + f];
        const float4* wr = reinterpret_cast<const float4*>(ws + f * HDIM + cg * 16);
        float4 w0 = wr[0], w1 = wr[1], w2 = wr[2], w3 = wr[3];
        #pragma unroll
        for (int k = 0; k < 4; k++) {
            acc[k][0]  += a[k] * w0.x;  acc[k][1]  += a[k] * w0.y;
            acc[k][2]  += a[k] * w0.z;  acc[k][3]  += a[k] * w0.w;
            acc[k][4]  += a[k] * w1.x;  acc[k][5]  += a[k] * w1.y;
            acc[k][6]  += a[k] * w1.z;  acc[k][7]  += a[k] * w1.w;
            acc[k][8]  += a[k] * w2.x;  acc[k][9]  += a[k] * w2.y;
            acc[k][10] += a[k] * w2.z;  acc[k][11] += a[k] * w2.w;
            acc[k][12] += a[k] * w3.x;  acc[k][13] += a[k] * w3.y;
            acc[k][14] += a[k] * w3.z;  acc[k][15] += a[k] * w3.w;
        }
    }
    #pragma unroll
    for (int j = 0; j < 16; j++) {
        const int col = cg * 16 + j;
        #pragma unroll
        for (int k = 0; k < 4; k++)
            outT[(size_t)col * NNODES + n0 + lane + 32 * k] = __float2half_rn(acc[k][j]);
    }
}

// ===================== host =====================
typedef CUresult (*PFN_encodeTiled)(CUtensorMap*, CUtensorMapDataType, cuuint32_t, void*,
                                    const cuuint64_t*, const cuuint64_t*, const cuuint32_t*,
                                    const cuuint32_t*, CUtensorMapInterleave, CUtensorMapSwizzle,
                                    CUtensorMapL2promotion, CUtensorMapFloatOOBfill);

extern "C" void kernel_launch(void* const* d_in, const int* in_sizes, int n_in,
                              void* d_out, int out_size) {
    const float* x   = (const float*)d_in[0];
    const float* adj = (const float*)d_in[1];
    const float* w1  = (const float*)d_in[2];
    const float* b1  = (const float*)d_in[3];
    const float* w2  = (const float*)d_in[4];
    const float* b2  = (const float*)d_in[5];
    const float* w3  = (const float*)d_in[6];
    const float* b3  = (const float*)d_in[7];
    float* out = (float*)d_out;

    void* bufB = nullptr;
    void* bufH = nullptr;
    cudaGetSymbolAddress(&bufB, g_bufB);
    cudaGetSymbolAddress(&bufH, g_bufH);

    void* fn = nullptr;
    cudaDriverEntryPointQueryResult qres;
    cudaGetDriverEntryPointByVersion("cuTensorMapEncodeTiled", &fn, 12000,
                                     cudaEnableDefault, &qres);
    PFN_encodeTiled encode = (PFN_encodeTiled)fn;

    CUtensorMap tmA{}, tmB{};
    {
        cuuint64_t dims[2]   = {NNODES, NNODES};
        cuuint64_t stride[1] = {NNODES * sizeof(float)};
        cuuint32_t box[2]    = {32, TILE_M};
        cuuint32_t es[2]     = {1, 1};
        encode(&tmA, CU_TENSOR_MAP_DATA_TYPE_FLOAT32, 2, (void*)adj, dims, stride, box, es,
               CU_TENSOR_MAP_INTERLEAVE_NONE, CU_TENSOR_MAP_SWIZZLE_128B,
               CU_TENSOR_MAP_L2_PROMOTION_L2_128B, CU_TENSOR_MAP_FLOAT_OOB_FILL_NONE);
    }
    {
        cuuint64_t dims[2]   = {NNODES, HDIM};
        cuuint64_t stride[1] = {NNODES * sizeof(__half)};
        cuuint32_t box[2]    = {64, TILE_N};   // 64 f16 = 128B rows (SW128)
        cuuint32_t es[2]     = {1, 1};
        encode(&tmB, CU_TENSOR_MAP_DATA_TYPE_FLOAT16, 2, bufB, dims, stride, box, es,
               CU_TENSOR_MAP_INTERLEAVE_NONE, CU_TENSOR_MAP_SWIZZLE_128B,
               CU_TENSOR_MAP_L2_PROMOTION_L2_128B, CU_TENSOR_MAP_FLOAT_OOB_FILL_NONE);
    }

    cudaFuncSetAttribute(gcn_big_gemm, cudaFuncAttributeMaxDynamicSharedMemorySize, SMEM_TOTAL);
    cudaFuncSetAttribute(gcn_big_gemm_head, cudaFuncAttributeMaxDynamicSharedMemorySize, SMEM_TOTAL);
    cudaFuncSetAttribute(gcn_in_gemm, cudaFuncAttributeMaxDynamicSharedMemorySize, IN_SMEM);

    // 1) t1^T (fp16)
    gcn_in_gemm<<<NNODES / 128, 256, IN_SMEM>>>(x, w1, (__half*)bufB);
    // 2) h1 = relu(adj @ t1 + b1)
    gcn_big_gemm<<<NNODES / TILE_M, BIG_THREADS, SMEM_TOTAL>>>(tmA, tmB, b1, (float*)bufH);
    // 3) t2^T (fp16)
    gcn_in_gemm<<<NNODES / 128, 256, IN_SMEM>>>((const float*)bufH, w2, (__half*)bufB);
    // 4) out = relu(adj @ t2 + b2) @ w3 + b3   (head fused into epilogue)
    gcn_big_gemm_head<<<NNODES / TILE_M, BIG_THREADS, SMEM_TOTAL>>>(tmA, tmB, b2, w3, b3, out);
}

// round 17
// speedup vs baseline: 3.8834x; 1.0065x over previous
#include <cuda_runtime.h>
#include <cuda.h>
#include <cuda_fp16.h>
#include <cstdint>

// ===================== constants =====================
#define NNODES   16384
#define HDIM     128
#define TILE_M   128
#define TILE_N   128
#define KSUPER   64             // K elems per super-stage (2 fp32 A boxes + 1 fp16 B box)
#define SSTAGES  4
#define SITERS   (NNODES / KSUPER)   // 256

#define A_SS_BYTES (TILE_M * KSUPER * 4)   // 32768 (fp32)
#define B_SS_BYTES (TILE_N * KSUPER * 2)   // 16384 (fp16)
#define SS_TX      (A_SS_BYTES + B_SS_BYTES)  // 49152

// smem layout (dynamic)
#define SM_FULL    0      // SSTAGES mbarriers (8B each)
#define SM_DONE    64     // SSTAGES mbarriers
#define SM_A       1024
#define SM_B       (SM_A + SSTAGES * A_SS_BYTES)     // 132096
#define SMEM_TOTAL (SM_B + SSTAGES * B_SS_BYTES)     // 197632

#define BIG_THREADS 288   // warps 0-7 compute (4x2 grid of 32x64 tiles), warp 8 TMA

// in_gemm smem: w tile 128x128 + x tile 128x129 (pad -> conflict-free)
#define XS_PAD  129
#define IN_SMEM ((HDIM * HDIM + HDIM * XS_PAD) * 4)   // 131584

// scratch (allocation-free rule: __device__ globals)
__device__ __align__(1024) __half g_bufB[128UL * 16384];  // t1^T / t2^T  [H][N] fp16
__device__ __align__(1024) float  g_bufH[16384UL * 128];  // h1           [N][H]

// ===================== PTX helpers =====================
__device__ __forceinline__ uint32_t smem_u32(const void* p) {
    uint32_t a;
    asm("{ .reg .u64 t; cvta.to.shared.u64 t, %1; cvt.u32.u64 %0, t; }" : "=r"(a) : "l"(p));
    return a;
}

#define MBAR_INIT(addr, cnt) \
    asm volatile("mbarrier.init.shared.b64 [%0], %1;" :: "r"(addr), "r"(cnt) : "memory")
#define MBAR_EXPECT_TX(addr, bytes) \
    asm volatile("mbarrier.arrive.expect_tx.shared.b64 _, [%0], %1;" :: "r"(addr), "r"(bytes) : "memory")
#define MBAR_ARRIVE(addr) \
    asm volatile("mbarrier.arrive.shared.b64 _, [%0];" :: "r"(addr) : "memory")
#define BAR_SYNC(id, n) \
    asm volatile("bar.sync %0, %1;" :: "r"(id), "r"(n) : "memory")

#define MBAR_WAIT(addr, parity) do {                                            \
    uint32_t _m = (addr), _p = (parity), _d;                                    \
    asm volatile("{\n\t.reg .pred p;\n\t"                                       \
        "mbarrier.try_wait.parity.acquire.cta.shared::cta.b64 p, [%1], %2;\n\t" \
        "selp.b32 %0, 1, 0, p;\n\t}" : "=r"(_d) : "r"(_m), "r"(_p) : "memory"); \
    if (!_d) {                                                                  \
        asm volatile("{\n\t.reg .pred P1;\n\t"                                  \
        "WL%=:\n\t"                                                             \
        "mbarrier.try_wait.parity.acquire.cta.shared::cta.b64 P1, [%0], %1, 0x989680;\n\t" \
        "@P1 bra.uni WD%=;\n\t"                                                 \
        "bra.uni WL%=;\n\t"                                                     \
        "WD%=:\n\t}" :: "r"(_m), "r"(_p) : "memory");                           \
    } } while (0)

__device__ __forceinline__ void tma_2d(uint32_t smem_dst, const CUtensorMap* map,
                                       int32_t cx, int32_t cy, uint32_t mbar) {
    asm volatile(
        "cp.async.bulk.tensor.2d.shared::cta.global.tile.mbarrier::complete_tx::bytes "
        "[%0], [%1, {%2, %3}], [%4];"
        :: "r"(smem_dst), "l"(map), "r"(cx), "r"(cy), "r"(mbar) : "memory");
}

// pack two fp32 -> f16x2 {lo=a, hi=b}
__device__ __forceinline__ uint32_t pack_f16x2(float a, float b) {
    uint32_t r;
    asm("cvt.rn.f16x2.f32 %0, %1, %2;" : "=r"(r) : "f"(b), "f"(a));
    return r;
}

__device__ __forceinline__ void mma_f16(float* c, const uint32_t* a, uint32_t b0, uint32_t b1) {
    asm volatile("mma.sync.aligned.m16n8k16.row.col.f32.f16.f16.f32 "
        "{%0,%1,%2,%3}, {%4,%5,%6,%7}, {%8,%9}, {%0,%1,%2,%3};"
        : "+f"(c[0]), "+f"(c[1]), "+f"(c[2]), "+f"(c[3])
        : "r"(a[0]), "r"(a[1]), "r"(a[2]), "r"(a[3]), "r"(b0), "r"(b1));
}

__device__ __forceinline__ float shfl_xor_f(float v, int m) {
    float r;
    asm("shfl.sync.bfly.b32 %0, %1, %2, 0x1F, 0xFFFFFFFF;" : "=f"(r) : "f"(v), "r"(m));
    return r;
}

// packed fp32x2 FMA: d = a*b + d  (two independent fp32 RN FMAs; Blackwell)
__device__ __forceinline__ void fma_x2(uint64_t& d, uint64_t a, uint64_t b) {
    asm("fma.rn.f32x2 %0, %1, %2, %0;" : "+l"(d) : "l"(a), "l"(b));
}
__device__ __forceinline__ uint64_t pack_f32x2(float lo, float hi) {
    uint64_t r;
    asm("mov.b64 %0, {%1, %2};" : "=l"(r) : "f"(lo), "f"(hi));
    return r;
}
__device__ __forceinline__ void unpack_f32x2(float& lo, float& hi, uint64_t v) {
    asm("mov.b64 {%0, %1}, %2;" : "=f"(lo), "=f"(hi) : "l"(v));
}

// ===================== big GEMM mainloop (shared by both variants) =====================
// HEAD=0: epilogue writes relu(acc+bias) fp32 tile to `out` (h1).
// HEAD=1: epilogue computes out[m][c] = b3[c] + sum_n relu(acc+bias)[m][n]*w3[n][c].
template <int HEAD>
__device__ __forceinline__ void big_gemm_body(
    const CUtensorMap& tmA, const CUtensorMap& tmB,
    const float* __restrict__ bias, float* __restrict__ out,
    const float* __restrict__ w3, const float* __restrict__ b3,
    char* smem) {
    const uint32_t base = smem_u32(smem);
    const int tid  = threadIdx.x;
    const int wid  = tid >> 5;
    const int lane = tid & 31;
    const int m0   = blockIdx.x * TILE_M;

    if (tid == 0) {
        for (int s = 0; s < SSTAGES; s++) {
            MBAR_INIT(base + SM_FULL + s * 8, 1);
            MBAR_INIT(base + SM_DONE + s * 8, 8);
        }
    }
    __syncthreads();

    if (wid == 8) {
        // -------- TMA producer --------
        if (lane == 0) {
            const CUtensorMap* pA = &tmA;
            const CUtensorMap* pB = &tmB;
            int ss = 0, ph = 1;
            for (int i = 0; i < SITERS; i++) {
                MBAR_WAIT(base + SM_DONE + ss * 8, (uint32_t)ph);
                uint32_t full = base + SM_FULL + ss * 8;
                MBAR_EXPECT_TX(full, SS_TX);
                uint32_t aslot = base + SM_A + ss * A_SS_BYTES;
                uint32_t bslot = base + SM_B + ss * B_SS_BYTES;
                int k0 = i * KSUPER;
                tma_2d(aslot,         pA, k0,      m0, full);
                tma_2d(aslot + 16384, pA, k0 + 32, m0, full);
                tma_2d(bslot,         pB, k0,      0,  full);
                if (++ss == SSTAGES) { ss = 0; ph ^= 1; }
            }
        }
        return;
    }

    // -------- compute warps --------
    const int g  = lane >> 2;     // 0..7
    const int tg = lane & 3;      // 0..3
    const int wm = wid >> 1;      // 0..3  (m: 32-row band)
    const int wn = wid & 1;       // 0..1  (n: 64-col band)
    const uint32_t xorv = (uint32_t)g << 4;

    const uint32_t rAbase = (uint32_t)(wm * 32 + g) * 128;
    const uint32_t rBbase = (uint32_t)(wn * 64 + g) * 128;

    uint32_t cA[2][2];
    #pragma unroll
    for (int s = 0; s < 2; s++) {
        cA[s][0] = ((uint32_t)(s * 64 + 8 * tg)) ^ xorv;
        cA[s][1] = ((uint32_t)(s * 64 + 8 * tg + 32)) ^ xorv;
    }
    uint32_t cB[4][2];
    #pragma unroll
    for (int kb = 0; kb < 4; kb++) {
        cB[kb][0] = ((uint32_t)(32 * kb + 4 * tg)) ^ xorv;
        cB[kb][1] = ((uint32_t)(32 * kb + 16 + 4 * tg)) ^ xorv;
    }

    float acc[2][8][4];
    #pragma unroll
    for (int mi = 0; mi < 2; mi++)
        #pragma unroll
        for (int ni = 0; ni < 8; ni++)
            #pragma unroll
            for (int q = 0; q < 4; q++) acc[mi][ni][q] = 0.0f;

    uint32_t Af[2][2][4];
    uint32_t Bf[2][8][2];

    auto ldA = [&](uint32_t af[2][4], const char* astg, int kb) {
        const char* ab = astg + ((kb >> 1) << 14);
        const uint32_t* c = cA[kb & 1];
        #pragma unroll
        for (int mi = 0; mi < 2; mi++) {
            const char* r0 = ab + rAbase + mi * 2048;
            uint2 lo0 = *(const uint2*)(r0 + c[0]);
            uint2 lo1 = *(const uint2*)(r0 + 1024 + c[0]);
            uint2 hi0 = *(const uint2*)(r0 + c[1]);
            uint2 hi1 = *(const uint2*)(r0 + 1024 + c[1]);
            af[mi][0] = pack_f16x2(__uint_as_float(lo0.x), __uint_as_float(lo0.y));
            af[mi][1] = pack_f16x2(__uint_as_float(lo1.x), __uint_as_float(lo1.y));
            af[mi][2] = pack_f16x2(__uint_as_float(hi0.x), __uint_as_float(hi0.y));
            af[mi][3] = pack_f16x2(__uint_as_float(hi1.x), __uint_as_float(hi1.y));
        }
    };
    auto ldB = [&](uint32_t bf[8][2], const char* bstg, int kb) {
        #pragma unroll
        for (int ni = 0; ni < 8; ni++) {
            bf[ni][0] = *(const uint32_t*)(bstg + rBbase + ni * 1024 + cB[kb][0]);
            bf[ni][1] = *(const uint32_t*)(bstg + rBbase + ni * 1024 + cB[kb][1]);
        }
    };
    auto mmab = [&](const uint32_t af[2][4], const uint32_t bf[8][2]) {
        #pragma unroll
        for (int mi = 0; mi < 2; mi++)
            #pragma unroll
            for (int ni = 0; ni < 8; ni++)
                mma_f16(acc[mi][ni], af[mi], bf[ni][0], bf[ni][1]);
    };

    int ss = 0, ph = 0;
    const char* astg = smem + SM_A;
    const char* bstg = smem + SM_B;

    MBAR_WAIT(base + SM_FULL, 0u);
    ldB(Bf[0], bstg, 0);
    ldA(Af[0], astg, 0);
    ldB(Bf[1], bstg, 1);
    ldA(Af[1], astg, 1);

    for (int i = 0; i < SITERS; i++) {
        mmab(Af[0], Bf[0]);
        ldB(Bf[0], bstg, 2);
        ldA(Af[0], astg, 2);
        mmab(Af[1], Bf[1]);
        ldB(Bf[1], bstg, 3);
        ldA(Af[1], astg, 3);
        mmab(Af[0], Bf[0]);
        int ssn = ss + 1, phn = ph;
        if (ssn == SSTAGES) { ssn = 0; phn ^= 1; }
        const char* nastg = smem + SM_A + ssn * A_SS_BYTES;
        const char* nbstg = smem + SM_B + ssn * B_SS_BYTES;
        if (i < SITERS - 1) {
            MBAR_WAIT(base + SM_FULL + ssn * 8, (uint32_t)phn);
            ldB(Bf[0], nbstg, 0);
            ldA(Af[0], nastg, 0);
        }
        mmab(Af[1], Bf[1]);
        if (lane == 0) MBAR_ARRIVE(base + SM_DONE + ss * 8);
        if (i < SITERS - 1) {
            ldB(Bf[1], nbstg, 1);
            ldA(Af[1], nastg, 1);
        }
        astg = nastg; bstg = nbstg; ss = ssn; ph = phn;
    }

    if (HEAD == 0) {
        // -------- epilogue: bias + relu, write fp32 h tile --------
        #pragma unroll
        for (int ni = 0; ni < 8; ni++) {
            const int c0 = wn * 64 + ni * 8 + tg * 2;
            const float bb0 = __ldg(&bias[c0]);
            const float bb1 = __ldg(&bias[c0 + 1]);
            #pragma unroll
            for (int mi = 0; mi < 2; mi++) {
                const int r0 = m0 + wm * 32 + mi * 16 + g;
                float2 v0, v1;
                v0.x = fmaxf(acc[mi][ni][0] + bb0, 0.0f);
                v0.y = fmaxf(acc[mi][ni][1] + bb1, 0.0f);
                v1.x = fmaxf(acc[mi][ni][2] + bb0, 0.0f);
                v1.y = fmaxf(acc[mi][ni][3] + bb1, 0.0f);
                *reinterpret_cast<float2*>(out + (size_t)r0 * HDIM + c0) = v0;
                *reinterpret_cast<float2*>(out + (size_t)(r0 + 8) * HDIM + c0) = v1;
            }
        }
    } else {
        // -------- fused head epilogue: out[m][c] = b3[c] + sum_n relu(h)[m][n]*w3[n][c]
        float s[2][2][2];   // [mi][h(0: row r0, 1: row r0+8)][class]
        #pragma unroll
        for (int mi = 0; mi < 2; mi++)
            #pragma unroll
            for (int h = 0; h < 2; h++) { s[mi][h][0] = 0.0f; s[mi][h][1] = 0.0f; }

        #pragma unroll
        for (int ni = 0; ni < 8; ni++) {
            const int c0 = wn * 64 + ni * 8 + tg * 2;
            const float bb0 = __ldg(&bias[c0]);
            const float bb1 = __ldg(&bias[c0 + 1]);
            const float w00 = __ldg(&w3[c0 * 2 + 0]),     w01 = __ldg(&w3[c0 * 2 + 1]);
            const float w10 = __ldg(&w3[(c0 + 1) * 2 + 0]), w11 = __ldg(&w3[(c0 + 1) * 2 + 1]);
            #pragma unroll
            for (int mi = 0; mi < 2; mi++) {
                float h0 = fmaxf(acc[mi][ni][0] + bb0, 0.0f);
                float h1 = fmaxf(acc[mi][ni][1] + bb1, 0.0f);
                s[mi][0][0] += h0 * w00 + h1 * w10;
                s[mi][0][1] += h0 * w01 + h1 * w11;
                float h2 = fmaxf(acc[mi][ni][2] + bb0, 0.0f);
                float h3 = fmaxf(acc[mi][ni][3] + bb1, 0.0f);
                s[mi][1][0] += h2 * w00 + h3 * w10;
                s[mi][1][1] += h2 * w01 + h3 * w11;
            }
        }
        // reduce over tg (4 lanes within each g-group)
        #pragma unroll
        for (int mi = 0; mi < 2; mi++)
            #pragma unroll
            for (int h = 0; h < 2; h++)
                #pragma unroll
                for (int c = 0; c < 2; c++) {
                    float v = s[mi][h][c];
                    v += shfl_xor_f(v, 1);
                    v += shfl_xor_f(v, 2);
                    s[mi][h][c] = v;
                }
        // cross-wn reduction via recycled pipeline smem (TMA warp has exited)
        float* red = (float*)(smem + SM_B);   // [128 rows][2 classes]
        if (wn == 0 && tg == 0) {
            #pragma unroll
            for (int mi = 0; mi < 2; mi++)
                #pragma unroll
                for (int h = 0; h < 2; h++) {
                    const int row = wm * 32 + mi * 16 + h * 8 + g;
                    red[row * 2 + 0] = s[mi][h][0];
                    red[row * 2 + 1] = s[mi][h][1];
                }
        }
        BAR_SYNC(1, 256);
        if (wn == 1 && tg == 0) {
            #pragma unroll
            for (int mi = 0; mi < 2; mi++)
                #pragma unroll
                for (int h = 0; h < 2; h++) {
                    const int row = wm * 32 + mi * 16 + h * 8 + g;
                    float2 o;
                    o.x = s[mi][h][0] + red[row * 2 + 0] + __ldg(&b3[0]);
                    o.y = s[mi][h][1] + red[row * 2 + 1] + __ldg(&b3[1]);
                    *reinterpret_cast<float2*>(out + (size_t)(m0 + row) * 2) = o;
                }
        }
    }
}

__global__ void __launch_bounds__(BIG_THREADS, 1)
gcn_big_gemm(const __grid_constant__ CUtensorMap tmA,
             const __grid_constant__ CUtensorMap tmB,
             const float* __restrict__ bias,
             float* __restrict__ out) {
    extern __shared__ __align__(1024) char smem[];
    big_gemm_body<0>(tmA, tmB, bias, out, nullptr, nullptr, smem);
}

__global__ void __launch_bounds__(BIG_THREADS, 1)
gcn_big_gemm_head(const __grid_constant__ CUtensorMap tmA,
                  const __grid_constant__ CUtensorMap tmB,
                  const float* __restrict__ bias,
                  const float* __restrict__ w3,
                  const float* __restrict__ b3,
                  float* __restrict__ out) {
    extern __shared__ __align__(1024) char smem[];
    big_gemm_body<1>(tmA, tmB, bias, out, w3, b3, smem);
}

// ===================== small GEMM: outT[n][node] = sum_f in[node][f] * w[f][n] =====================
// Output stored as fp16 (RN) = pre-rounded B operand for the big GEMM.
// Inner product uses packed fma.rn.f32x2 (two fp32 RN FMAs per instruction,
// bit-identical numerics, half the FMA instruction stream).
__global__ void __launch_bounds__(256)
gcn_in_gemm(const float* __restrict__ in, const float* __restrict__ w, __half* __restrict__ outT) {
    extern __shared__ float sm[];
    float* ws = sm;                       // [128][128]
    float* xs = sm + HDIM * HDIM;         // [128][129] padded
    const int tid = threadIdx.x;
    const int n0 = blockIdx.x * 128;

    for (int i = tid; i < (HDIM * HDIM) / 4; i += 256)
        reinterpret_cast<float4*>(ws)[i] = reinterpret_cast<const float4*>(w)[i];
    {
        const int col = tid & 127;
        const int r0  = tid >> 7;
        for (int r = r0; r < 128; r += 2)
            xs[r * XS_PAD + col] = in[(size_t)(n0 + r) * HDIM + col];
    }
    __syncthreads();

    const int cg   = tid >> 5;
    const int lane = tid & 31;

    // packed accumulators: accP[k][jp] holds cols (jp*2, jp*2+1)
    uint64_t accP[4][8];
    #pragma unroll
    for (int k = 0; k < 4; k++)
        #pragma unroll
        for (int jp = 0; jp < 8; jp++) accP[k][jp] = pack_f32x2(0.0f, 0.0f);

    #pragma unroll 4
    for (int f = 0; f < HDIM; f++) {
        uint64_t aP[4];
        #pragma unroll
        for (int k = 0; k < 4; k++) {
            float a = xs[(lane + 32 * k) * XS_PAD + f];
            aP[k] = pack_f32x2(a, a);
        }
        const ulonglong2* wr = reinterpret_cast<const ulonglong2*>(ws + f * HDIM + cg * 16);
        ulonglong2 w01 = wr[0], w23 = wr[1], w45 = wr[2], w67 = wr[3];
        #pragma unroll
        for (int k = 0; k < 4; k++) {
            fma_x2(accP[k][0], aP[k], w01.x);
            fma_x2(accP[k][1], aP[k], w01.y);
            fma_x2(accP[k][2], aP[k], w23.x);
            fma_x2(accP[k][3], aP[k], w23.y);
            fma_x2(accP[k][4], aP[k], w45.x);
            fma_x2(accP[k][5], aP[k], w45.y);
            fma_x2(accP[k][6], aP[k], w67.x);
            fma_x2(accP[k][7], aP[k], w67.y);
        }
    }
    #pragma unroll
    for (int jp = 0; jp < 8; jp++) {
        #pragma unroll
        for (int k = 0; k < 4; k++) {
            float lo, hi;
            unpack_f32x2(lo, hi, accP[k][jp]);
            const int col0 = cg * 16 + jp * 2;
            outT[(size_t)col0 * NNODES + n0 + lane + 32 * k]       = __float2half_rn(lo);
            outT[(size_t)(col0 + 1) * NNODES + n0 + lane + 32 * k] = __float2half_rn(hi);
        }
    }
}

// ===================== host =====================
typedef CUresult (*PFN_encodeTiled)(CUtensorMap*, CUtensorMapDataType, cuuint32_t, void*,
                                    const cuuint64_t*, const cuuint64_t*, const cuuint32_t*,
                                    const cuuint32_t*, CUtensorMapInterleave, CUtensorMapSwizzle,
                                    CUtensorMapL2promotion, CUtensorMapFloatOOBfill);

extern "C" void kernel_launch(void* const* d_in, const int* in_sizes, int n_in,
                              void* d_out, int out_size) {
    const float* x   = (const float*)d_in[0];
    const float* adj = (const float*)d_in[1];
    const float* w1  = (const float*)d_in[2];
    const float* b1  = (const float*)d_in[3];
    const float* w2  = (const float*)d_in[4];
    const float* b2  = (const float*)d_in[5];
    const float* w3  = (const float*)d_in[6];
    const float* b3  = (const float*)d_in[7];
    float* out = (float*)d_out;

    void* bufB = nullptr;
    void* bufH = nullptr;
    cudaGetSymbolAddress(&bufB, g_bufB);
    cudaGetSymbolAddress(&bufH, g_bufH);

    void* fn = nullptr;
    cudaDriverEntryPointQueryResult qres;
    cudaGetDriverEntryPointByVersion("cuTensorMapEncodeTiled", &fn, 12000,
                                     cudaEnableDefault, &qres);
    PFN_encodeTiled encode = (PFN_encodeTiled)fn;

    CUtensorMap tmA{}, tmB{};
    {
        cuuint64_t dims[2]   = {NNODES, NNODES};
        cuuint64_t stride[1] = {NNODES * sizeof(float)};
        cuuint32_t box[2]    = {32, TILE_M};
        cuuint32_t es[2]     = {1, 1};
        encode(&tmA, CU_TENSOR_MAP_DATA_TYPE_FLOAT32, 2, (void*)adj, dims, stride, box, es,
               CU_TENSOR_MAP_INTERLEAVE_NONE, CU_TENSOR_MAP_SWIZZLE_128B,
               CU_TENSOR_MAP_L2_PROMOTION_L2_128B, CU_TENSOR_MAP_FLOAT_OOB_FILL_NONE);
    }
    {
        cuuint64_t dims[2]   = {NNODES, HDIM};
        cuuint64_t stride[1] = {NNODES * sizeof(__half)};
        cuuint32_t box[2]    = {64, TILE_N};   // 64 f16 = 128B rows (SW128)
        cuuint32_t es[2]     = {1, 1};
        encode(&tmB, CU_TENSOR_MAP_DATA_TYPE_FLOAT16, 2, bufB, dims, stride, box, es,
               CU_TENSOR_MAP_INTERLEAVE_NONE, CU_TENSOR_MAP_SWIZZLE_128B,
               CU_TENSOR_MAP_L2_PROMOTION_L2_128B, CU_TENSOR_MAP_FLOAT_OOB_FILL_NONE);
    }

    cudaFuncSetAttribute(gcn_big_gemm, cudaFuncAttributeMaxDynamicSharedMemorySize, SMEM_TOTAL);
    cudaFuncSetAttribute(gcn_big_gemm_head, cudaFuncAttributeMaxDynamicSharedMemorySize, SMEM_TOTAL);
    cudaFuncSetAttribute(gcn_in_gemm, cudaFuncAttributeMaxDynamicSharedMemorySize, IN_SMEM);

    // 1) t1^T (fp16)
    gcn_in_gemm<<<NNODES / 128, 256, IN_SMEM>>>(x, w1, (__half*)bufB);
    // 2) h1 = relu(adj @ t1 + b1)
    gcn_big_gemm<<<NNODES / TILE_M, BIG_THREADS, SMEM_TOTAL>>>(tmA, tmB, b1, (float*)bufH);
    // 3) t2^T (fp16)
    gcn_in_gemm<<<NNODES / 128, 256, IN_SMEM>>>((const float*)bufH, w2, (__half*)bufB);
    // 4) out = relu(adj @ t2 + b2) @ w3 + b3   (head fused into epilogue)
    gcn_big_gemm_head<<<NNODES / TILE_M, BIG_THREADS, SMEM_TOTAL>>>(tmA, tmB, b2, w3, b3, out);
}